// round 5
// baseline (speedup 1.0000x reference)
#include <cuda_runtime.h>

// Problem constants
#define T_STEPS 1024
#define BATCH   128
#define FEAT    64
#define HID     256
#define KDIM    (HID + FEAT)   // 320
#define NCTA    128
#define TPB     512
#define NW      16             // warps per CTA
#define KH      16             // h-part k's per warp
#define KX      4              // x-part k's per warp
#define TF      (T_STEPS * FEAT)

// ---------------- device scratch ----------------
__device__ float g_xT[T_STEPS * FEAT * BATCH];   // 32MB: xT[t][f][b]
__device__ float g_S[2 * HID * BATCH];           // double-buffered h, k-major
__device__ volatile unsigned g_flags[NCTA];
__device__ unsigned g_done;

// packed f32x2 FMA (2 fp32 MACs per instr)
#define FMA2(D, S, W) asm("fma.rn.f32x2 %0, %1, %2, %0;" : "+l"(D) : "l"(S), "l"(W))

__device__ __forceinline__ ulonglong2 ldcg128(const float* p) {
    ulonglong2 v;
    asm volatile("ld.global.cg.v2.u64 {%0,%1}, [%2];"
                 : "=l"(v.x), "=l"(v.y) : "l"(p));
    return v;
}
__device__ __forceinline__ void stcg32(float* p, float v) {
    asm volatile("st.global.cg.f32 [%0], %1;" :: "l"(p), "f"(v) : "memory");
}
__device__ __forceinline__ unsigned ldacq(const unsigned* p) {
    unsigned v;
    asm volatile("ld.acquire.gpu.global.u32 %0, [%1];" : "=r"(v) : "l"(p));
    return v;
}

__device__ __forceinline__ float sigf(float x)  { return 1.f / (1.f + __expf(-x)); }
__device__ __forceinline__ float tanhff(float x){ return 2.f / (1.f + __expf(-2.f * x)) - 1.f; }

// ---------------- input transpose: ts[b][t][f] -> xT[t][f][b] ----------------
__global__ void transpose_x_kernel(const float* __restrict__ ts) {
    __shared__ float tile[FEAT * 129];
    int t = blockIdx.x;
    for (int i = threadIdx.x; i < BATCH * FEAT; i += 256) {
        int b = i >> 6, f = i & 63;
        tile[f * 129 + b] = ts[b * TF + t * FEAT + f];
    }
    __syncthreads();
    for (int i = threadIdx.x; i < BATCH * FEAT; i += 256) {
        int f = i >> 7, b = i & 127;
        g_xT[t * (FEAT * BATCH) + f * BATCH + b] = tile[f * 129 + b];
    }
}

// ---------------- per-warp producer wait ----------------
// Warp consuming k-rows [klo, klo+16) needs CTAs [klo/2, klo/2+8) at >= val.
__device__ __forceinline__ void warp_wait(int firstCta, unsigned val) {
    int lane = threadIdx.x & 31;
    if (lane < 8) {
        const unsigned* p = (const unsigned*)&g_flags[firstCta + lane];
        while (ldacq(p) < val) { }
    }
    __syncwarp();
}

// ---------------- weight slice load into SMEM (duplicated for f32x2) ----------------
__device__ __forceinline__ void load_weights(const float* __restrict__ Whh,
                                             const float* __restrict__ Wih,
                                             const float* __restrict__ bias,
                                             float* w2, float* bias_s, int j0) {
    for (int idx = threadIdx.x; idx < KDIM * 8; idx += TPB) {
        int k = idx >> 3, r = idx & 7;
        int jj = r >> 2, gate = r & 3;
        int rg = gate * HID + j0 + jj;
        float v = (k < HID) ? Whh[rg * HID + k] : Wih[rg * FEAT + (k - HID)];
        w2[(k * 8 + r) * 2 + 0] = v;
        w2[(k * 8 + r) * 2 + 1] = v;
    }
    if (threadIdx.x < 8) {
        int r = threadIdx.x;
        bias_s[r] = bias[(r & 3) * HID + j0 + (r >> 2)];
    }
}

// 8 FMA2 rows against one state value pair, weights via 4x LDS.128
__device__ __forceinline__ void fma_rows(unsigned long long* accA, unsigned long long* accB,
                                         ulonglong2 sv, const float* wk) {
    ulonglong2 w01 = *(const ulonglong2*)(wk + 0);
    ulonglong2 w23 = *(const ulonglong2*)(wk + 4);
    ulonglong2 w45 = *(const ulonglong2*)(wk + 8);
    ulonglong2 w67 = *(const ulonglong2*)(wk + 12);
    FMA2(accA[0], sv.x, w01.x); FMA2(accB[0], sv.y, w01.x);
    FMA2(accA[1], sv.x, w01.y); FMA2(accB[1], sv.y, w01.y);
    FMA2(accA[2], sv.x, w23.x); FMA2(accB[2], sv.y, w23.x);
    FMA2(accA[3], sv.x, w23.y); FMA2(accB[3], sv.y, w23.y);
    FMA2(accA[4], sv.x, w45.x); FMA2(accB[4], sv.y, w45.x);
    FMA2(accA[5], sv.x, w45.y); FMA2(accB[5], sv.y, w45.y);
    FMA2(accA[6], sv.x, w67.x); FMA2(accB[6], sv.y, w67.x);
    FMA2(accA[7], sv.x, w67.y); FMA2(accB[7], sv.y, w67.y);
}

// ---------------- accumulate x-part (off critical path) ----------------
__device__ __forceinline__ void accum_x(int t, unsigned long long* accA,
                                        unsigned long long* accB,
                                        const float* __restrict__ w2, int ks, int b0) {
    const float* xp = g_xT + t * (FEAT * BATCH) + b0;
    const int klo = HID + ks * KX;
    ulonglong2 sv[KX];
#pragma unroll
    for (int i = 0; i < KX; ++i) sv[i] = ldcg128(xp + (klo + i - HID) * BATCH);
#pragma unroll
    for (int i = 0; i < KX; ++i) fma_rows(accA, accB, sv[i], w2 + (klo + i) * 16);
}

// ---------------- h-part GEMM (critical path) ----------------
template <bool OUT>
__device__ __forceinline__ void gemm_h(const float* __restrict__ Scur,
                                       const float* __restrict__ w2,
                                       const float* __restrict__ wout2,
                                       unsigned long long* accA, unsigned long long* accB,
                                       unsigned long long& oA, unsigned long long& oB,
                                       int klo, int b0) {
    const float* sp = Scur + b0;
    ulonglong2 sv[8];
#pragma unroll
    for (int i = 0; i < 8; ++i) sv[i] = ldcg128(sp + (klo + i) * BATCH);
#pragma unroll
    for (int i = 0; i < 8; ++i) {
        ulonglong2 cur = sv[i];
        sv[i] = ldcg128(sp + (klo + 8 + i) * BATCH);
        fma_rows(accA, accB, cur, w2 + (klo + i) * 16);
        if (OUT) {
            unsigned long long wo = *(const unsigned long long*)(wout2 + (klo + i) * 2);
            FMA2(oA, cur.x, wo); FMA2(oB, cur.y, wo);
        }
    }
#pragma unroll
    for (int i = 0; i < 8; ++i) {
        fma_rows(accA, accB, sv[i], w2 + (klo + 8 + i) * 16);
        if (OUT) {
            unsigned long long wo = *(const unsigned long long*)(wout2 + (klo + 8 + i) * 2);
            FMA2(oA, sv[i].x, wo); FMA2(oB, sv[i].y, wo);
        }
    }
}

// ---------------- SMEM layout (floats) ----------------
#define SMEM_FLOATS 25480
#define SMEM_BYTES  (SMEM_FLOATS * 4)

__global__ void __launch_bounds__(TPB, 1) lstm_persistent_kernel(
    const float* __restrict__ Wih_e, const float* __restrict__ Whh_e, const float* __restrict__ b_e,
    const float* __restrict__ Wih_d, const float* __restrict__ Whh_d, const float* __restrict__ b_d,
    const float* __restrict__ Wout, const float* __restrict__ bout,
    float* __restrict__ out)
{
    extern __shared__ float sm[];
    float* w2      = sm;            // 5120
    float* wout2   = sm + 5120;     // 512
    float* red     = sm + 5632;     // 16384
    float* red_o   = sm + 22016;    // 2048
    float* gates_s = sm + 24064;    // 1024
    float* c_s     = sm + 25088;    // 256
    float* osum_s  = sm + 25344;    // 128
    float* bias_s  = sm + 25472;    // 8

    const int cta = blockIdx.x;
    const int tid = threadIdx.x;
    const int j0  = cta * 2;
    const int ks  = tid >> 5;                      // warp id 0..15
    const int ksr = (ks + cta) & 15;               // rotated k-slice
    const int klo = ksr * KH;
    const int firstCta = klo >> 1;                 // first producer CTA of this slice
    const int b0  = (tid & 31) << 2;               // 4 batches per thread

    load_weights(Whh_e, Wih_e, b_e, w2, bias_s, j0);
    if (tid < BATCH) {
        stcg32(&g_S[(j0 + 0) * BATCH + tid], 0.f);
        stcg32(&g_S[(j0 + 1) * BATCH + tid], 0.f);
        c_s[tid]         = 0.f;
        c_s[BATCH + tid] = 0.f;
    }

    // initial publish (flag = 1)
    __syncthreads();
    if (tid == 0) { __threadfence(); g_flags[cta] = 1u; }

    unsigned long long accA[8], accB[8], oA = 0ull, oB = 0ull;
#pragma unroll
    for (int r = 0; r < 8; ++r) { accA[r] = 0ull; accB[r] = 0ull; }
    accum_x(0, accA, accB, w2, ks, b0);

    unsigned step = 1u;
    int cur = 0;

    // ================= encoder =================
    for (int t = 0; t < T_STEPS; ++t) {
        warp_wait(firstCta, step);                       // per-warp, acquire
        const float* Scur = g_S + cur * HID * BATCH;
        float*       Snxt = g_S + (cur ^ 1) * HID * BATCH;

        gemm_h<false>(Scur, w2, wout2, accA, accB, oA, oB, klo, b0);

#pragma unroll
        for (int r = 0; r < 8; ++r) {
            ulonglong2 v; v.x = accA[r]; v.y = accB[r];
            *(ulonglong2*)(red + (ks * 8 + r) * BATCH + b0) = v;
        }
        __syncthreads();                                 // (A)

        { // gates reduce (all 512 threads)
            int r  = tid >> 6;
            int b2 = (tid & 63) << 1;
            float2 s = make_float2(0.f, 0.f);
#pragma unroll
            for (int q = 0; q < NW; ++q) {
                float2 p = *(const float2*)(red + (q * 8 + r) * BATCH + b2);
                s.x += p.x; s.y += p.y;
            }
            float bb = bias_s[r];
            s.x += bb; s.y += bb;
            *(float2*)(gates_s + r * BATCH + b2) = s;
        }
        __syncthreads();                                 // (B)

        // next-step x prefetch-accumulate (everyone; warps 8-15 race ahead)
#pragma unroll
        for (int r = 0; r < 8; ++r) { accA[r] = 0ull; accB[r] = 0ull; }

        if (tid < 256) { // pointwise + early publish by warps 0-7
            int jj = tid >> 7, b = tid & 127;
            float gi = gates_s[(jj * 4 + 0) * BATCH + b];
            float gf = gates_s[(jj * 4 + 1) * BATCH + b];
            float gg = gates_s[(jj * 4 + 2) * BATCH + b];
            float go = gates_s[(jj * 4 + 3) * BATCH + b];
            float c  = sigf(gf) * c_s[jj * BATCH + b] + sigf(gi) * tanhff(gg);
            c_s[jj * BATCH + b] = c;
            stcg32(&Snxt[(j0 + jj) * BATCH + b], sigf(go) * tanhff(c));
            asm volatile("bar.sync 1, 256;" ::: "memory");
            if (tid == 0) { __threadfence(); g_flags[cta] = step + 1u; }
        }

        if (t < T_STEPS - 1) accum_x(t + 1, accA, accB, w2, ks, b0);
        ++step;
        cur ^= 1;
    }

    // ================= switch to decoder weights =================
    __syncthreads();
    load_weights(Whh_d, Wih_d, b_d, w2, bias_s, j0);
    const bool has_out = (cta < FEAT);
    for (int k = tid; k < HID; k += TPB) {
        float v = has_out ? Wout[cta * HID + k] : 0.f;
        wout2[k * 2 + 0] = v;
        wout2[k * 2 + 1] = v;
    }
    float bout_f = has_out ? bout[cta] : 0.f;
    __syncthreads();

#pragma unroll
    for (int r = 0; r < 8; ++r) { accA[r] = 0ull; accB[r] = 0ull; }
    accum_x(T_STEPS - 1, accA, accB, w2, ks, b0);
    oA = 0ull; oB = 0ull;

    // ================= decoder (reversed time) =================
    for (int tt = 0; tt < T_STEPS; ++tt) {
        int t = T_STEPS - 1 - tt;
        warp_wait(firstCta, step);
        const float* Scur = g_S + cur * HID * BATCH;
        float*       Snxt = g_S + (cur ^ 1) * HID * BATCH;

        gemm_h<true>(Scur, w2, wout2, accA, accB, oA, oB, klo, b0);

#pragma unroll
        for (int r = 0; r < 8; ++r) {
            ulonglong2 v; v.x = accA[r]; v.y = accB[r];
            *(ulonglong2*)(red + (ks * 8 + r) * BATCH + b0) = v;
        }
        { ulonglong2 v; v.x = oA; v.y = oB;
          *(ulonglong2*)(red_o + ks * BATCH + b0) = v; }
        __syncthreads();                                 // (A)

        { // gates reduce
            int r  = tid >> 6;
            int b2 = (tid & 63) << 1;
            float2 s = make_float2(0.f, 0.f);
#pragma unroll
            for (int q = 0; q < NW; ++q) {
                float2 p = *(const float2*)(red + (q * 8 + r) * BATCH + b2);
                s.x += p.x; s.y += p.y;
            }
            float bb = bias_s[r];
            s.x += bb; s.y += bb;
            *(float2*)(gates_s + r * BATCH + b2) = s;
        }
        if (tid >= 448) { // osum reduce (warps 14-15), red_o complete since (A)
            int b2 = (tid - 448) << 1;
            float2 s = make_float2(0.f, 0.f);
#pragma unroll
            for (int q = 0; q < NW; ++q) {
                float2 p = *(const float2*)(red_o + q * BATCH + b2);
                s.x += p.x; s.y += p.y;
            }
            *(float2*)(osum_s + b2) = s;
        }
        __syncthreads();                                 // (B)

#pragma unroll
        for (int r = 0; r < 8; ++r) { accA[r] = 0ull; accB[r] = 0ull; }
        oA = 0ull; oB = 0ull;

        if (tid < 256) { // pointwise + early publish
            int jj = tid >> 7, b = tid & 127;
            float gi = gates_s[(jj * 4 + 0) * BATCH + b];
            float gf = gates_s[(jj * 4 + 1) * BATCH + b];
            float gg = gates_s[(jj * 4 + 2) * BATCH + b];
            float go = gates_s[(jj * 4 + 3) * BATCH + b];
            float c  = sigf(gf) * c_s[jj * BATCH + b] + sigf(gi) * tanhff(gg);
            c_s[jj * BATCH + b] = c;
            stcg32(&Snxt[(j0 + jj) * BATCH + b], sigf(go) * tanhff(c));
            asm volatile("bar.sync 1, 256;" ::: "memory");
            if (tid == 0) { __threadfence(); g_flags[cta] = step + 1u; }
        } else if (tid < 384) { // output emit (warps 8-11), off critical path
            if (has_out) {
                int b = tid - 256;
                out[b * TF + t * FEAT + cta] = osum_s[b] + bout_f;
            }
        }

        if (tt < T_STEPS - 1) accum_x(t - 1, accA, accB, w2, ks, b0);
        ++step;
        cur ^= 1;
    }

    // ---- reset barrier state for graph replays ----
    __syncthreads();
    if (tid == 0) {
        atomicAdd(&g_done, 1u);
        if (cta == 0) {
            while (*((volatile unsigned*)&g_done) < NCTA) { }
            for (int i = 0; i < NCTA; ++i) g_flags[i] = 0u;
            __threadfence();
            g_done = 0u;
        }
    }
}

// ---------------- launch ----------------
extern "C" void kernel_launch(void* const* d_in, const int* in_sizes, int n_in,
                              void* d_out, int out_size) {
    const float* ts    = (const float*)d_in[0];
    const float* Wih_e = (const float*)d_in[1];
    const float* Whh_e = (const float*)d_in[2];
    const float* b_e   = (const float*)d_in[3];
    const float* Wih_d = (const float*)d_in[4];
    const float* Whh_d = (const float*)d_in[5];
    const float* b_d   = (const float*)d_in[6];
    const float* Wout  = (const float*)d_in[7];
    const float* bout  = (const float*)d_in[8];
    float* out = (float*)d_out;

    cudaFuncSetAttribute(lstm_persistent_kernel,
                         cudaFuncAttributeMaxDynamicSharedMemorySize, SMEM_BYTES);

    transpose_x_kernel<<<T_STEPS, 256>>>(ts);
    lstm_persistent_kernel<<<NCTA, TPB, SMEM_BYTES>>>(
        Wih_e, Whh_e, b_e, Wih_d, Whh_d, b_d, Wout, bout, out);
}

// round 7
// speedup vs baseline: 2.5984x; 2.5984x over previous
#include <cuda_runtime.h>

// Problem constants
#define T_STEPS 1024
#define BATCH   128
#define FEAT    64
#define HID     256
#define KDIM    (HID + FEAT)   // 320
#define NCTA    128
#define TPB     512
#define NW      16             // warps per CTA
#define KH      16             // h-part k's per warp (16*16=256)
#define KX      4              // x-part k's per warp (16*4=64)
#define GQ      32             // batch per group (4 groups)
#define JH      8              // h-columns per CTA (32 slices * 8 = 256)
#define TF      (T_STEPS * FEAT)

// ---------------- device scratch ----------------
__device__ float g_xT[T_STEPS * FEAT * BATCH];   // 32MB: xT[t][f][b]
__device__ float g_S[2 * HID * BATCH];           // double-buffered h, k-major: S[buf][k][b]
__device__ volatile unsigned g_flags[NCTA];
__device__ unsigned g_done;

// packed f32x2 ops
#define FMA2(D, S, W) asm("fma.rn.f32x2 %0, %1, %2, %0;" : "+l"(D) : "l"(S), "l"(W))
#define ADD2(D, A, B) asm("add.rn.f32x2 %0, %1, %2;" : "=l"(D) : "l"(A), "l"(B))

__device__ __forceinline__ float ldcg32(const float* p) {
    float v; asm volatile("ld.global.cg.f32 %0, [%1];" : "=f"(v) : "l"(p)); return v;
}
__device__ __forceinline__ void stcg32(float* p, float v) {
    asm volatile("st.global.cg.f32 [%0], %1;" :: "l"(p), "f"(v) : "memory");
}
__device__ __forceinline__ unsigned long long dup2(float s) {
    unsigned long long d; unsigned u = __float_as_uint(s);
    asm("mov.b64 %0, {%1, %1};" : "=l"(d) : "r"(u));
    return d;
}
__device__ __forceinline__ float2 unpack2(unsigned long long v) {
    float2 r;
    asm("mov.b64 {%0, %1}, %2;" : "=f"(r.x), "=f"(r.y) : "l"(v));
    return r;
}

__device__ __forceinline__ float sigf(float x)  { return 1.f / (1.f + __expf(-x)); }
__device__ __forceinline__ float tanhff(float x){ return 2.f / (1.f + __expf(-2.f * x)) - 1.f; }

// ---------------- input transpose: ts[b][t][f] -> xT[t][f][b] ----------------
__global__ void transpose_x_kernel(const float* __restrict__ ts) {
    __shared__ float tile[FEAT * 129];
    int t = blockIdx.x;
    for (int i = threadIdx.x; i < BATCH * FEAT; i += 256) {
        int b = i >> 6, f = i & 63;
        tile[f * 129 + b] = ts[b * TF + t * FEAT + f];
    }
    __syncthreads();
    for (int i = threadIdx.x; i < BATCH * FEAT; i += 256) {
        int f = i >> 7, b = i & 127;
        g_xT[t * (FEAT * BATCH) + f * BATCH + b] = tile[f * 129 + b];
    }
}

// ---------------- weights: w2[k][r] with r = jj*4+gate, rows packed in pairs ----------------
// rg (global gate row) = gate*HID + j0 + jj
__device__ __forceinline__ void load_weights(const float* __restrict__ Whh,
                                             const float* __restrict__ Wih,
                                             const float* __restrict__ bias,
                                             float* w2, float* bias2, int j0) {
    for (int idx = threadIdx.x; idx < KDIM * 32; idx += TPB) {
        int k = idx >> 5, r = idx & 31;
        int jj = r >> 2, gate = r & 3;
        int rg = gate * HID + j0 + jj;
        float v = (k < HID) ? Whh[rg * HID + k] : Wih[rg * FEAT + (k - HID)];
        w2[k * 32 + r] = v;
    }
    if (threadIdx.x < 32) {
        int r = threadIdx.x;
        int jj = r >> 2, gate = r & 3;
        bias2[r] = bias[gate * HID + j0 + jj];   // bias2 indexed same as rows
    }
}

// ---------------- 16 packed FMA rows (32 gate rows) for one state scalar ----------------
__device__ __forceinline__ void fma_rows32(unsigned long long* acc, unsigned long long d,
                                           const float* wk) {
    const ulonglong2* wp = (const ulonglong2*)wk;
#pragma unroll
    for (int p = 0; p < 8; ++p) {
        ulonglong2 w = wp[p];
        FMA2(acc[2 * p + 0], d, w.x);
        FMA2(acc[2 * p + 1], d, w.y);
    }
}

// ---------------- x-part accumulation (off critical path) ----------------
__device__ __forceinline__ void accum_x(int t, unsigned long long* acc,
                                        const float* __restrict__ w2,
                                        int ks, int qb_lane) {
    const float* xp = g_xT + t * (FEAT * BATCH) + qb_lane;
    const int klo = HID + ks * KX;
    float sv[KX];
#pragma unroll
    for (int i = 0; i < KX; ++i) sv[i] = ldcg32(xp + (klo + i - HID) * BATCH);
#pragma unroll
    for (int i = 0; i < KX; ++i) fma_rows32(acc, dup2(sv[i]), w2 + (klo + i) * 32);
}

// ---------------- h-part GEMM (critical path) ----------------
template <bool OUT>
__device__ __forceinline__ void gemm_h(const float* __restrict__ Scur,
                                       const float* __restrict__ w2,
                                       const float* __restrict__ wout2,
                                       unsigned long long* acc, unsigned long long& o,
                                       int klo, int qb_lane) {
    const float* sp = Scur + qb_lane;
    float sv[KH];
#pragma unroll
    for (int i = 0; i < KH; ++i) sv[i] = ldcg32(sp + (klo + i) * BATCH);
#pragma unroll
    for (int i = 0; i < KH; ++i) {
        unsigned long long d = dup2(sv[i]);
        fma_rows32(acc, d, w2 + (klo + i) * 32);
        if (OUT) {
            unsigned long long wo = *(const unsigned long long*)(wout2 + (klo + i) * 2);
            FMA2(o, d, wo);
        }
    }
}

// ---------------- SMEM layout (floats) ----------------
//  w2     10240 @ 0        (320 k * 32 rows)
//  wout2    512 @ 10240    (256 k * 2 features)
//  red    16384 @ 10752    (16 slices * 16 rowpairs * 32 b * 2)
//  red_o   1024 @ 27136    (16 slices * 32 b * 2)
//  gates   1024 @ 28160    (16 rowpairs * 32 b * 2)
//  c_s      256 @ 29184    (8 jj * 32 b)
//  bias2     32 @ 29440
#define SMEM_FLOATS 29472
#define SMEM_BYTES  (SMEM_FLOATS * 4)

__global__ void __launch_bounds__(TPB, 1) lstm_persistent_kernel(
    const float* __restrict__ Wih_e, const float* __restrict__ Whh_e, const float* __restrict__ b_e,
    const float* __restrict__ Wih_d, const float* __restrict__ Whh_d, const float* __restrict__ b_d,
    const float* __restrict__ Wout, const float* __restrict__ bout,
    float* __restrict__ out)
{
    extern __shared__ float sm[];
    float* w2    = sm;
    float* wout2 = sm + 10240;
    float* red   = sm + 10752;
    float* red_o = sm + 27136;
    float* gates = sm + 28160;
    float* c_s   = sm + 29184;
    float* bias2 = sm + 29440;

    const int cta   = blockIdx.x;
    const int tid   = threadIdx.x;
    const int grp   = cta >> 5;          // batch-quarter group 0..3
    const int slice = cta & 31;          // H-slice 0..31
    const int qb0   = grp * GQ;          // batch offset of this group
    const int j0    = slice * JH;        // first h-column owned
    const int ks    = tid >> 5;          // warp 0..15
    const int lane  = tid & 31;
    const int ksr   = (ks + slice) & 15; // rotated k-slice (spread L2 bursts)
    const int klo   = ksr * KH;
    const int qb_lane = qb0 + lane;
    const int gbase = grp << 5;          // first flag of this group

    load_weights(Whh_e, Wih_e, b_e, w2, bias2, j0);
    if (tid < 256) {
        int jj = tid >> 5, b = tid & 31;
        stcg32(&g_S[(j0 + jj) * BATCH + qb0 + b], 0.f);
        c_s[jj * GQ + b] = 0.f;
    }
    __syncthreads();
    if (tid == 0) { __threadfence(); g_flags[cta] = 1u; }

    unsigned long long acc[16], o = 0ull;
#pragma unroll
    for (int p = 0; p < 16; ++p) acc[p] = 0ull;
    accum_x(0, acc, w2, ks, qb_lane);

    unsigned step = 1u;
    int cur = 0;

    // ================= encoder =================
    for (int t = 0; t < T_STEPS; ++t) {
        // wait on our group's 32 producers
        if (tid < 32) { while (g_flags[gbase + tid] < step) { } }
        __syncthreads();
        __threadfence();

        const float* Scur = g_S + cur * HID * BATCH;
        float*       Snxt = g_S + (cur ^ 1) * HID * BATCH;

        gemm_h<false>(Scur, w2, wout2, acc, o, klo, qb_lane);

#pragma unroll
        for (int p = 0; p < 16; ++p)
            *(unsigned long long*)(red + ((ks * 16 + p) * GQ + lane) * 2) = acc[p];
        __syncthreads();                                 // (A)

        { // reduce 16 slices -> gates (packed rowpairs)
            int rp = tid >> 5, b = tid & 31;
            unsigned long long a = *(const unsigned long long*)(bias2 + rp * 2);
#pragma unroll
            for (int q = 0; q < NW; ++q) {
                unsigned long long v = *(const unsigned long long*)(red + ((q * 16 + rp) * GQ + b) * 2);
                ADD2(a, a, v);
            }
            *(unsigned long long*)(gates + (rp * GQ + b) * 2) = a;
        }
        __syncthreads();                                 // (B)

#pragma unroll
        for (int p = 0; p < 16; ++p) acc[p] = 0ull;

        if (tid < 256) { // pointwise
            int jj = tid >> 5, b = tid & 31;
            float2 g_if = unpack2(*(const unsigned long long*)(gates + ((2 * jj) * GQ + b) * 2));
            float2 g_go = unpack2(*(const unsigned long long*)(gates + ((2 * jj + 1) * GQ + b) * 2));
            float c = sigf(g_if.y) * c_s[jj * GQ + b] + sigf(g_if.x) * tanhff(g_go.x);
            c_s[jj * GQ + b] = c;
            stcg32(&Snxt[(j0 + jj) * BATCH + qb0 + b], sigf(g_go.y) * tanhff(c));
        }
        __syncthreads();
        if (tid == 0) { __threadfence(); g_flags[cta] = step + 1u; }

        if (t < T_STEPS - 1) accum_x(t + 1, acc, w2, ks, qb_lane);
        ++step;
        cur ^= 1;
    }

    // ================= switch to decoder weights =================
    __syncthreads();
    load_weights(Whh_d, Wih_d, b_d, w2, bias2, j0);
    const int f0 = slice * 2;                       // 2 output features per CTA
    for (int k = tid; k < HID; k += TPB) {
        wout2[k * 2 + 0] = Wout[(f0 + 0) * HID + k];
        wout2[k * 2 + 1] = Wout[(f0 + 1) * HID + k];
    }
    float bo0 = bout[f0], bo1 = bout[f0 + 1];
    __syncthreads();

#pragma unroll
    for (int p = 0; p < 16; ++p) acc[p] = 0ull;
    o = 0ull;
    accum_x(T_STEPS - 1, acc, w2, ks, qb_lane);

    // ================= decoder (reversed time) =================
    for (int tt = 0; tt < T_STEPS; ++tt) {
        int t = T_STEPS - 1 - tt;
        if (tid < 32) { while (g_flags[gbase + tid] < step) { } }
        __syncthreads();
        __threadfence();

        const float* Scur = g_S + cur * HID * BATCH;
        float*       Snxt = g_S + (cur ^ 1) * HID * BATCH;

        gemm_h<true>(Scur, w2, wout2, acc, o, klo, qb_lane);

#pragma unroll
        for (int p = 0; p < 16; ++p)
            *(unsigned long long*)(red + ((ks * 16 + p) * GQ + lane) * 2) = acc[p];
        *(unsigned long long*)(red_o + (ks * GQ + lane) * 2) = o;
        __syncthreads();                                 // (A)

        { // gates reduce
            int rp = tid >> 5, b = tid & 31;
            unsigned long long a = *(const unsigned long long*)(bias2 + rp * 2);
#pragma unroll
            for (int q = 0; q < NW; ++q) {
                unsigned long long v = *(const unsigned long long*)(red + ((q * 16 + rp) * GQ + b) * 2);
                ADD2(a, a, v);
            }
            *(unsigned long long*)(gates + (rp * GQ + b) * 2) = a;
        }
        if (tid >= 256 && tid < 288) { // warp 8: osum reduce + direct emit (off critical path)
            int b = tid - 256;
            unsigned long long a = 0ull;
#pragma unroll
            for (int q = 0; q < NW; ++q) {
                unsigned long long v = *(const unsigned long long*)(red_o + (q * GQ + b) * 2);
                ADD2(a, a, v);
            }
            float2 ov = unpack2(a);
            float2 res; res.x = ov.x + bo0; res.y = ov.y + bo1;
            *(float2*)(out + (qb0 + b) * TF + t * FEAT + f0) = res;
        }
        __syncthreads();                                 // (B)

#pragma unroll
        for (int p = 0; p < 16; ++p) acc[p] = 0ull;
        o = 0ull;

        if (tid < 256) { // pointwise
            int jj = tid >> 5, b = tid & 31;
            float2 g_if = unpack2(*(const unsigned long long*)(gates + ((2 * jj) * GQ + b) * 2));
            float2 g_go = unpack2(*(const unsigned long long*)(gates + ((2 * jj + 1) * GQ + b) * 2));
            float c = sigf(g_if.y) * c_s[jj * GQ + b] + sigf(g_if.x) * tanhff(g_go.x);
            c_s[jj * GQ + b] = c;
            stcg32(&Snxt[(j0 + jj) * BATCH + qb0 + b], sigf(g_go.y) * tanhff(c));
        }
        __syncthreads();
        if (tid == 0) { __threadfence(); g_flags[cta] = step + 1u; }

        if (tt < T_STEPS - 1) accum_x(t - 1, acc, w2, ks, qb_lane);
        ++step;
        cur ^= 1;
    }

    // ---- reset barrier state for graph replays ----
    __syncthreads();
    if (tid == 0) {
        atomicAdd(&g_done, 1u);
        if (cta == 0) {
            while (*((volatile unsigned*)&g_done) < NCTA) { }
            for (int i = 0; i < NCTA; ++i) g_flags[i] = 0u;
            __threadfence();
            g_done = 0u;
        }
    }
}

// ---------------- launch ----------------
extern "C" void kernel_launch(void* const* d_in, const int* in_sizes, int n_in,
                              void* d_out, int out_size) {
    const float* ts    = (const float*)d_in[0];
    const float* Wih_e = (const float*)d_in[1];
    const float* Whh_e = (const float*)d_in[2];
    const float* b_e   = (const float*)d_in[3];
    const float* Wih_d = (const float*)d_in[4];
    const float* Whh_d = (const float*)d_in[5];
    const float* b_d   = (const float*)d_in[6];
    const float* Wout  = (const float*)d_in[7];
    const float* bout  = (const float*)d_in[8];
    float* out = (float*)d_out;

    cudaFuncSetAttribute(lstm_persistent_kernel,
                         cudaFuncAttributeMaxDynamicSharedMemorySize, SMEM_BYTES);

    transpose_x_kernel<<<T_STEPS, 256>>>(ts);
    lstm_persistent_kernel<<<NCTA, TPB, SMEM_BYTES>>>(
        Wih_e, Whh_e, b_e, Wih_d, Whh_d, b_d, Wout, bout, out);
}

// round 11
// speedup vs baseline: 2.7217x; 1.0475x over previous
#include <cuda_runtime.h>

// Problem constants
#define T_STEPS 1024
#define BATCH   128
#define FEAT    64
#define HID     256
#define KDIM    (HID + FEAT)   // 320
#define NCTA    128
#define TPB     512
#define NW      16             // warps per CTA
#define KH      16             // h-part k's per warp (16*16=256)
#define KX      4              // x-part k's per warp (16*4=64)
#define GQ      32             // batch per group (4 groups)
#define JH      8              // h-columns per CTA
#define TF      (T_STEPS * FEAT)

// ---------------- device scratch ----------------
__device__ float g_xT[T_STEPS * FEAT * BATCH];   // 32MB: xT[t][f][b]
__device__ float g_S[2 * HID * BATCH];           // double-buffered h, k-major: S[buf][k][b]
__device__ volatile unsigned g_flags[NCTA];
__device__ unsigned g_done;

typedef unsigned long long ull;

// packed f32x2 ops
#define FMA2(D, S, W) asm("fma.rn.f32x2 %0, %1, %2, %0;" : "+l"(D) : "l"(S), "l"(W))

__device__ __forceinline__ float4 ldcg128v(const float* p) {
    float4 v;
    asm volatile("ld.global.cg.v4.f32 {%0,%1,%2,%3}, [%4];"
                 : "=f"(v.x), "=f"(v.y), "=f"(v.z), "=f"(v.w) : "l"(p));
    return v;
}
__device__ __forceinline__ void stcg32(float* p, float v) {
    asm volatile("st.global.cg.f32 [%0], %1;" :: "l"(p), "f"(v) : "memory");
}

__device__ __forceinline__ float sigf(float x)  { return 1.f / (1.f + __expf(-x)); }
__device__ __forceinline__ float tanhff(float x){ return 2.f / (1.f + __expf(-2.f * x)) - 1.f; }

// ---------------- input transpose: ts[b][t][f] -> xT[t][f][b] ----------------
__global__ void transpose_x_kernel(const float* __restrict__ ts) {
    __shared__ float tile[FEAT * 129];
    int t = blockIdx.x;
    for (int i = threadIdx.x; i < BATCH * FEAT; i += 256) {
        int b = i >> 6, f = i & 63;
        tile[f * 129 + b] = ts[b * TF + t * FEAT + f];
    }
    __syncthreads();
    for (int i = threadIdx.x; i < BATCH * FEAT; i += 256) {
        int f = i >> 7, b = i & 127;
        g_xT[t * (FEAT * BATCH) + f * BATCH + b] = tile[f * 129 + b];
    }
}

// ---------------- weights: w2dup[k][i][rg] = float4(w[r],w[r],w[r+1],w[r+1]) ----------------
// local row r = jj*4 + gate (jj 0..7, gate 0..3); rg = r>>3, i = (r&7)>>1, lo = r&1
// address (floats): k*64 + i*16 + rg*4 + lo*2   -> rg-addresses 16B apart: conflict-free
__device__ __forceinline__ void load_weights(const float* __restrict__ Whh,
                                             const float* __restrict__ Wih,
                                             const float* __restrict__ bias,
                                             float* w2dup, float* bias_s, int j0) {
    for (int idx = threadIdx.x; idx < KDIM * 32; idx += TPB) {
        int k = idx >> 5, r = idx & 31;
        int jj = r >> 2, gate = r & 3;
        int rg = r >> 3, i = (r & 7) >> 1, lo = r & 1;
        int rgrow = gate * HID + j0 + jj;
        float v = (k < HID) ? Whh[rgrow * HID + k] : Wih[rgrow * FEAT + (k - HID)];
        w2dup[k * 64 + i * 16 + rg * 4 + lo * 2 + 0] = v;
        w2dup[k * 64 + i * 16 + rg * 4 + lo * 2 + 1] = v;
    }
    if (threadIdx.x < 32) {
        int r = threadIdx.x;
        int jj = r >> 2, gate = r & 3;
        bias_s[r] = bias[gate * HID + j0 + jj];
    }
}

// ---------------- one k contribution: 16 FMA2 against 4 LDS.128 ----------------
template <bool OUT>
__device__ __forceinline__ void kstep(float4 s, ull* acc, ull* o,
                                      const float* wk, const float* wo) {
    ulonglong2 ss = *(const ulonglong2*)&s;    // s01 = (b0,b1), s23 = (b2,b3)
#pragma unroll
    for (int i = 0; i < 4; ++i) {
        ulonglong2 w = *(const ulonglong2*)(wk + i * 16);   // rows 2i, 2i+1 (dup'd)
        FMA2(acc[4 * i + 0], ss.x, w.x); FMA2(acc[4 * i + 1], ss.y, w.x);
        FMA2(acc[4 * i + 2], ss.x, w.y); FMA2(acc[4 * i + 3], ss.y, w.y);
    }
    if (OUT) {
        ulonglong2 w = *(const ulonglong2*)wo;              // (f0 dup, f1 dup)
        FMA2(o[0], ss.x, w.x); FMA2(o[1], ss.y, w.x);
        FMA2(o[2], ss.x, w.y); FMA2(o[3], ss.y, w.y);
    }
}

// ---------------- x-part accumulation (off critical path) ----------------
__device__ __forceinline__ void accum_x(int t, ull* acc, ull* o,
                                        const float* __restrict__ w2dup,
                                        int ks, int qb4, int rg4) {
    const float* xp = g_xT + t * (FEAT * BATCH) + qb4;
    const int klo = HID + ks * KX;
    float4 sv[KX];
#pragma unroll
    for (int i = 0; i < KX; ++i) sv[i] = ldcg128v(xp + (klo + i - HID) * BATCH);
#pragma unroll
    for (int i = 0; i < KX; ++i)
        kstep<false>(sv[i], acc, o, w2dup + (klo + i) * 64 + rg4, (const float*)0);
}

// ---------------- h-part GEMM (critical path) ----------------
template <bool OUT>
__device__ __forceinline__ void gemm_h(const float* __restrict__ Scur,
                                       const float* __restrict__ w2dup,
                                       const float* __restrict__ woutd,
                                       ull* acc, ull* o,
                                       int klo, int qb4, int rg4) {
    const float* sp = Scur + qb4;
    float4 sv[8];
#pragma unroll
    for (int i = 0; i < 8; ++i) sv[i] = ldcg128v(sp + (klo + i) * BATCH);
#pragma unroll
    for (int i = 0; i < 8; ++i) {
        float4 s = sv[i];
        sv[i] = ldcg128v(sp + (klo + 8 + i) * BATCH);
        kstep<OUT>(s, acc, o, w2dup + (klo + i) * 64 + rg4, woutd + (klo + i) * 4);
    }
#pragma unroll
    for (int i = 0; i < 8; ++i)
        kstep<OUT>(sv[i], acc, o, w2dup + (klo + 8 + i) * 64 + rg4, woutd + (klo + 8 + i) * 4);
}

// ---------------- SMEM layout (floats) ----------------
//  w2dup   20480 @ 0       (320 k * 64)
//  woutdup  1024 @ 20480   (256 k * 4)
//  red     16384 @ 21504   (16 warps * 32 rows * 32 b)
//  red_o    1024 @ 37888   (2 f * 16 warps * 32 b)
//  c_s       256 @ 38912
//  bias_s     32 @ 39168
#define SMEM_FLOATS 39200
#define SMEM_BYTES  (SMEM_FLOATS * 4)

__global__ void __launch_bounds__(TPB, 1) lstm_persistent_kernel(
    const float* __restrict__ Wih_e, const float* __restrict__ Whh_e, const float* __restrict__ b_e,
    const float* __restrict__ Wih_d, const float* __restrict__ Whh_d, const float* __restrict__ b_d,
    const float* __restrict__ Wout, const float* __restrict__ bout,
    float* __restrict__ out)
{
    extern __shared__ float sm[];
    float* w2dup  = sm;
    float* woutd  = sm + 20480;
    float* red    = sm + 21504;
    float* red_o  = sm + 37888;
    float* c_s    = sm + 38912;
    float* bias_s = sm + 39168;

    const int cta   = blockIdx.x;
    const int tid   = threadIdx.x;
    const int grp   = cta >> 5;            // batch-quarter group 0..3
    const int slice = cta & 31;            // H-slice 0..31
    const int qb0   = grp * GQ;
    const int j0    = slice * JH;
    const int ks    = tid >> 5;            // warp 0..15
    const int lane  = tid & 31;
    const int rg    = lane >> 3;           // rowgroup 0..3
    const int bq    = lane & 7;            // batch-quad 0..7
    const int rg4   = rg * 4;
    const int ksr   = (ks + slice) & 15;   // rotated k-slice
    const int klo   = ksr * KH;
    const int qb4   = qb0 + bq * 4;
    const int gbase = grp << 5;

    load_weights(Whh_e, Wih_e, b_e, w2dup, bias_s, j0);
    if (tid < 256) {
        int jj = tid >> 5, b = tid & 31;
        stcg32(&g_S[(j0 + jj) * BATCH + qb0 + b], 0.f);
        c_s[jj * GQ + b] = 0.f;
    }
    __syncthreads();
    if (tid == 0) { __threadfence(); g_flags[cta] = 1u; }

    ull acc[16], o[4];
#pragma unroll
    for (int p = 0; p < 16; ++p) acc[p] = 0ull;
    accum_x(0, acc, o, w2dup, ks, qb4, rg4);

    unsigned step = 1u;
    int cur = 0;

    // ================= encoder =================
    for (int t = 0; t < T_STEPS; ++t) {
        if (tid < 32) { while (g_flags[gbase + tid] < step) { } }
        __syncthreads();
        __threadfence();

        const float* Scur = g_S + cur * HID * BATCH;
        float*       Snxt = g_S + (cur ^ 1) * HID * BATCH;

        gemm_h<false>(Scur, w2dup, woutd, acc, o, klo, qb4, rg4);

        // store partials: rows rg*8+rloc, batches bq*4..+3 (conflict-free ST.128)
#pragma unroll
        for (int rl = 0; rl < 8; ++rl) {
            ulonglong2 v; v.x = acc[rl * 2 + 0]; v.y = acc[rl * 2 + 1];
            *(ulonglong2*)(red + (ks * 32 + rg * 8 + rl) * GQ + bq * 4) = v;
        }
        __syncthreads();                                 // (A)

#pragma unroll
        for (int p = 0; p < 16; ++p) acc[p] = 0ull;

        if (tid < 256) { // fused reduce + pointwise
            int jj = tid >> 5, b = tid & 31;
            float gi = bias_s[jj * 4 + 0], gf = bias_s[jj * 4 + 1];
            float gg = bias_s[jj * 4 + 2], go = bias_s[jj * 4 + 3];
#pragma unroll
            for (int q = 0; q < NW; ++q) {
                const float* base = red + (q * 32 + jj * 4) * GQ + b;
                gi += base[0]; gf += base[GQ]; gg += base[2 * GQ]; go += base[3 * GQ];
            }
            float c = sigf(gf) * c_s[jj * GQ + b] + sigf(gi) * tanhff(gg);
            c_s[jj * GQ + b] = c;
            stcg32(&Snxt[(j0 + jj) * BATCH + qb0 + b], sigf(go) * tanhff(c));
            asm volatile("bar.sync 1, 256;" ::: "memory");
            if (tid == 0) { __threadfence(); g_flags[cta] = step + 1u; }
        }

        if (t < T_STEPS - 1) accum_x(t + 1, acc, o, w2dup, ks, qb4, rg4);
        ++step;
        cur ^= 1;
    }

    // ================= switch to decoder weights =================
    __syncthreads();
    load_weights(Whh_d, Wih_d, b_d, w2dup, bias_s, j0);
    const int f0 = slice * 2;
    for (int k = tid; k < HID; k += TPB) {
        float v0 = Wout[(f0 + 0) * HID + k];
        float v1 = Wout[(f0 + 1) * HID + k];
        woutd[k * 4 + 0] = v0; woutd[k * 4 + 1] = v0;
        woutd[k * 4 + 2] = v1; woutd[k * 4 + 3] = v1;
    }
    float bo0 = bout[f0], bo1 = bout[f0 + 1];
    __syncthreads();

#pragma unroll
    for (int p = 0; p < 16; ++p) acc[p] = 0ull;
#pragma unroll
    for (int p = 0; p < 4; ++p) o[p] = 0ull;
    accum_x(T_STEPS - 1, acc, o, w2dup, ks, qb4, rg4);

    // ================= decoder (reversed time) =================
    for (int tt = 0; tt < T_STEPS; ++tt) {
        int t = T_STEPS - 1 - tt;
        if (tid < 32) { while (g_flags[gbase + tid] < step) { } }
        __syncthreads();
        __threadfence();

        const float* Scur = g_S + cur * HID * BATCH;
        float*       Snxt = g_S + (cur ^ 1) * HID * BATCH;

        gemm_h<true>(Scur, w2dup, woutd, acc, o, klo, qb4, rg4);

#pragma unroll
        for (int rl = 0; rl < 8; ++rl) {
            ulonglong2 v; v.x = acc[rl * 2 + 0]; v.y = acc[rl * 2 + 1];
            *(ulonglong2*)(red + (ks * 32 + rg * 8 + rl) * GQ + bq * 4) = v;
        }
        if (rg == 0) { // output-projection partials (batches bq*4..+3)
            ulonglong2 v0; v0.x = o[0]; v0.y = o[1];
            ulonglong2 v1; v1.x = o[2]; v1.y = o[3];
            *(ulonglong2*)(red_o + ks * GQ + bq * 4) = v0;
            *(ulonglong2*)(red_o + 512 + ks * GQ + bq * 4) = v1;
        }
        __syncthreads();                                 // (A)

#pragma unroll
        for (int p = 0; p < 16; ++p) acc[p] = 0ull;
#pragma unroll
        for (int p = 0; p < 4; ++p) o[p] = 0ull;

        if (tid < 256) { // fused reduce + pointwise
            int jj = tid >> 5, b = tid & 31;
            float gi = bias_s[jj * 4 + 0], gf = bias_s[jj * 4 + 1];
            float gg = bias_s[jj * 4 + 2], go = bias_s[jj * 4 + 3];
#pragma unroll
            for (int q = 0; q < NW; ++q) {
                const float* base = red + (q * 32 + jj * 4) * GQ + b;
                gi += base[0]; gf += base[GQ]; gg += base[2 * GQ]; go += base[3 * GQ];
            }
            float c = sigf(gf) * c_s[jj * GQ + b] + sigf(gi) * tanhff(gg);
            c_s[jj * GQ + b] = c;
            stcg32(&Snxt[(j0 + jj) * BATCH + qb0 + b], sigf(go) * tanhff(c));
            asm volatile("bar.sync 1, 256;" ::: "memory");
            if (tid == 0) { __threadfence(); g_flags[cta] = step + 1u; }
        } else if (tid < 288) { // warp 8: osum reduce + direct emit (off critical path)
            int b = tid - 256;
            float s0 = 0.f, s1 = 0.f;
#pragma unroll
            for (int q = 0; q < NW; ++q) {
                s0 += red_o[q * GQ + b];
                s1 += red_o[512 + q * GQ + b];
            }
            float2 res; res.x = s0 + bo0; res.y = s1 + bo1;
            *(float2*)(out + (qb0 + b) * TF + t * FEAT + f0) = res;
        }

        if (tt < T_STEPS - 1) accum_x(t - 1, acc, o, w2dup, ks, qb4, rg4);
        ++step;
        cur ^= 1;
    }

    // ---- reset barrier state for graph replays ----
    __syncthreads();
    if (tid == 0) {
        atomicAdd(&g_done, 1u);
        if (cta == 0) {
            while (*((volatile unsigned*)&g_done) < NCTA) { }
            for (int i = 0; i < NCTA; ++i) g_flags[i] = 0u;
            __threadfence();
            g_done = 0u;
        }
    }
}

// ---------------- launch ----------------
extern "C" void kernel_launch(void* const* d_in, const int* in_sizes, int n_in,
                              void* d_out, int out_size) {
    const float* ts    = (const float*)d_in[0];
    const float* Wih_e = (const float*)d_in[1];
    const float* Whh_e = (const float*)d_in[2];
    const float* b_e   = (const float*)d_in[3];
    const float* Wih_d = (const float*)d_in[4];
    const float* Whh_d = (const float*)d_in[5];
    const float* b_d   = (const float*)d_in[6];
    const float* Wout  = (const float*)d_in[7];
    const float* bout  = (const float*)d_in[8];
    float* out = (float*)d_out;

    cudaFuncSetAttribute(lstm_persistent_kernel,
                         cudaFuncAttributeMaxDynamicSharedMemorySize, SMEM_BYTES);

    transpose_x_kernel<<<T_STEPS, 256>>>(ts);
    lstm_persistent_kernel<<<NCTA, TPB, SMEM_BYTES>>>(
        Wih_e, Whh_e, b_e, Wih_d, Whh_d, b_d, Wout, bout, out);
}